// round 1
// baseline (speedup 1.0000x reference)
#include <cuda_runtime.h>
#include <math.h>
#include <stdint.h>

// ---------------------------------------------------------------------------
// Problem constants
// ---------------------------------------------------------------------------
#define S_LEN 40
#define T_LEN 30
#define BB    64
#define EMBD  620
#define HIDN  1000
#define ATTD  1000
#define MXO   500
#define OUTV  30000
#define G3    3000            // 3*HID
#define E2    2000            // 2*HID
#define DXK   2620            // 2*HID + EMB
#define MXK   3620            // 3*HID + EMB
#define MX2   1000            // 2*MXO

// ---------------------------------------------------------------------------
// Workspace arena (device global; no cudaMalloc allowed)
// ---------------------------------------------------------------------------
static const size_t O_EMB = 0;                                   // S*B*EMB
static const size_t O_GXF = O_EMB + (size_t)S_LEN*BB*EMBD;       // S*B*G3
static const size_t O_GXB = O_GXF + (size_t)S_LEN*BB*G3;         // S*B*G3
static const size_t O_ENC = O_GXB + (size_t)S_LEN*BB*G3;         // S*B*E2
static const size_t O_EP  = O_ENC + (size_t)S_LEN*BB*E2;         // S*B*ATT
static const size_t O_PA  = O_EP  + (size_t)S_LEN*BB*ATTD;       // 8*B*G3 partials
static const size_t O_PB  = O_PA  + (size_t)8*BB*G3;             // 8*B*G3 partials
static const size_t O_H   = O_PB  + (size_t)8*BB*G3;             // B*HID
static const size_t O_HD  = O_H   + (size_t)BB*HIDN;             // B*HID (decoder h)
static const size_t O_HQ  = O_HD  + (size_t)BB*HIDN;             // B*ATT
static const size_t O_SC  = O_HQ  + (size_t)BB*ATTD;             // S*B
static const size_t O_AL  = O_SC  + (size_t)S_LEN*BB;            // S*B
static const size_t O_CTX = O_AL  + (size_t)S_LEN*BB;            // B*E2
static const size_t O_ET  = O_CTX + (size_t)BB*E2;               // B*EMB
static const size_t O_X   = O_ET  + (size_t)BB*EMBD;             // B*DXK
static const size_t O_MI  = O_X   + (size_t)BB*DXK;              // B*MXK
static const size_t O_T   = O_MI  + (size_t)BB*MXK;              // B*MX2
static const size_t O_TM  = O_T   + (size_t)BB*MX2;              // B*MXO
static const size_t ARENA = O_TM  + (size_t)BB*MXO;

__device__ float g_ws[ARENA];
__device__ int   g_inp[BB];

// ---------------------------------------------------------------------------
// Generic GEMM: C[M,N] = act(A[M,K(lda)] @ B[N,K]^T + bias)
// B element = Bp[n*ldb + boff + k]  (supports attn_w column slices)
// grid.z = split-K: partial z writes C + z*M*N (no bias/act when split>1)
// 64x64 tile, 256 threads, 4x4 micro tile.
// ---------------------------------------------------------------------------
__global__ void gemm_nt_k(const float* __restrict__ A, int lda,
                          const float* __restrict__ Bp, int ldb, int boff,
                          const float* __restrict__ bias,
                          float* __restrict__ C,
                          int M, int N, int K, int kc, int act)
{
    __shared__ float As[16][65];
    __shared__ float Bs[16][65];
    const int n0 = blockIdx.x * 64;
    const int m0 = blockIdx.y * 64;
    const int z  = blockIdx.z;
    const int k0 = z * kc;
    const int k1 = (k0 + kc < K) ? (k0 + kc) : K;
    float* Cz = C + (size_t)z * M * N;

    const int tid = threadIdx.x;
    const int tx = tid & 15;
    const int ty = tid >> 4;

    float acc[4][4];
#pragma unroll
    for (int i = 0; i < 4; i++)
#pragma unroll
        for (int j = 0; j < 4; j++) acc[i][j] = 0.f;

    for (int kt = k0; kt < k1; kt += 16) {
#pragma unroll
        for (int i = 0; i < 4; i++) {
            int e = tid + 256 * i;
            int m = e >> 4;
            int k = e & 15;
            int gk = kt + k;
            float av = 0.f, bv = 0.f;
            if (gk < k1) {
                int gm = m0 + m;
                if (gm < M) av = A[(size_t)gm * lda + gk];
                int gn = n0 + m;
                if (gn < N) bv = Bp[(size_t)gn * ldb + boff + gk];
            }
            As[k][m] = av;
            Bs[k][m] = bv;
        }
        __syncthreads();
#pragma unroll
        for (int kk = 0; kk < 16; kk++) {
            float av[4], bv[4];
#pragma unroll
            for (int i = 0; i < 4; i++) av[i] = As[kk][ty + 16 * i];
#pragma unroll
            for (int j = 0; j < 4; j++) bv[j] = Bs[kk][tx + 16 * j];
#pragma unroll
            for (int i = 0; i < 4; i++)
#pragma unroll
                for (int j = 0; j < 4; j++) acc[i][j] += av[i] * bv[j];
        }
        __syncthreads();
    }

    const bool fin = (gridDim.z == 1);
#pragma unroll
    for (int i = 0; i < 4; i++) {
        int r = m0 + ty + 16 * i;
        if (r >= M) continue;
#pragma unroll
        for (int j = 0; j < 4; j++) {
            int c = n0 + tx + 16 * j;
            if (c >= N) continue;
            float v = acc[i][j];
            if (fin) {
                if (bias) v += bias[c];
                if (act == 1) v = tanhf(v);
            }
            Cz[(size_t)r * N + c] = v;
        }
    }
}

// sum split-K partials + bias + optional tanh
__global__ void finalize_k(const float* __restrict__ parts, int nz,
                           const float* __restrict__ bias,
                           float* __restrict__ out, int MN, int N, int act)
{
    int i = blockIdx.x * blockDim.x + threadIdx.x;
    if (i >= MN) return;
    float v = 0.f;
    for (int z = 0; z < nz; z++) v += parts[(size_t)z * MN + i];
    if (bias) v += bias[i % N];
    if (act) v = tanhf(v);
    out[i] = v;
}

// GRU gate. gx/gh are [zx|zh] stacked partial [B,G3] buffers.
// h updated in place; optionally also written to eout[b*E2 + j].
__global__ void gru_gate_k(const float* __restrict__ gx, int zx, const float* __restrict__ bx,
                           const float* __restrict__ gh, int zh, const float* __restrict__ bh,
                           float* __restrict__ h, float* __restrict__ eout)
{
    int i = blockIdx.x * blockDim.x + threadIdx.x;
    if (i >= BB * HIDN) return;
    int b = i / HIDN, j = i % HIDN;
    float xr = 0.f, xz = 0.f, xn = 0.f, hr = 0.f, hz = 0.f, hn = 0.f;
    for (int z = 0; z < zx; z++) {
        const float* p = gx + ((size_t)z * BB + b) * G3;
        xr += p[j]; xz += p[HIDN + j]; xn += p[2 * HIDN + j];
    }
    if (bx) { xr += bx[j]; xz += bx[HIDN + j]; xn += bx[2 * HIDN + j]; }
    for (int z = 0; z < zh; z++) {
        const float* p = gh + ((size_t)z * BB + b) * G3;
        hr += p[j]; hz += p[HIDN + j]; hn += p[2 * HIDN + j];
    }
    hr += bh[j]; hz += bh[HIDN + j]; hn += bh[2 * HIDN + j];
    float r  = 1.f / (1.f + expf(-(xr + hr)));
    float zz = 1.f / (1.f + expf(-(xz + hz)));
    float n  = tanhf(xn + r * hn);
    float h2 = (1.f - zz) * n + zz * h[i];
    h[i] = h2;
    if (eout) eout[(size_t)b * E2 + j] = h2;
}

__global__ void embed_k(const float* __restrict__ table, const int* __restrict__ idx,
                        float* __restrict__ out, int rows, int E)
{
    int i = blockIdx.x * blockDim.x + threadIdx.x;
    if (i >= rows * E) return;
    int r = i / E, e = i % E;
    out[i] = table[(size_t)idx[r] * E + e];
}

__global__ void copy_inp_k(const int* __restrict__ trg, int* __restrict__ inp)
{
    inp[threadIdx.x] = trg[threadIdx.x];
}

// scores[s*B+b] = sum_a v[a]*tanh(hq[b,a] + ep[s,b,a] + ab[a]); one warp per (s,b)
__global__ void energy_k(const float* __restrict__ hq, const float* __restrict__ ep,
                         const float* __restrict__ ab, const float* __restrict__ v,
                         float* __restrict__ scores)
{
    int w = (blockIdx.x * blockDim.x + threadIdx.x) >> 5;
    int lane = threadIdx.x & 31;
    if (w >= S_LEN * BB) return;
    int b = w % BB;
    const float* eprow = ep + (size_t)w * ATTD;
    const float* hqrow = hq + (size_t)b * ATTD;
    float s = 0.f;
    for (int a = lane; a < ATTD; a += 32)
        s += v[a] * tanhf(hqrow[a] + eprow[a] + ab[a]);
#pragma unroll
    for (int o = 16; o; o >>= 1) s += __shfl_down_sync(0xffffffffu, s, o);
    if (lane == 0) scores[w] = s;
}

__global__ void softmax_k(const float* __restrict__ sc, float* __restrict__ al)
{
    int b = threadIdx.x;  // 64 threads
    float m = -1e30f;
    for (int s = 0; s < S_LEN; s++) m = fmaxf(m, sc[s * BB + b]);
    float sum = 0.f;
    for (int s = 0; s < S_LEN; s++) sum += expf(sc[s * BB + b] - m);
    float inv = 1.f / sum;
    for (int s = 0; s < S_LEN; s++) al[s * BB + b] = expf(sc[s * BB + b] - m) * inv;
}

__global__ void ctx_k(const float* __restrict__ al, const float* __restrict__ enc,
                      float* __restrict__ ctx)
{
    int i = blockIdx.x * blockDim.x + threadIdx.x;
    if (i >= BB * E2) return;
    int b = i / E2, h = i % E2;
    float s = 0.f;
    for (int si = 0; si < S_LEN; si++)
        s += al[si * BB + b] * enc[((size_t)si * BB + b) * E2 + h];
    ctx[i] = s;
}

__global__ void concat_x_k(const float* __restrict__ et, const float* __restrict__ ctx,
                           float* __restrict__ x)
{
    int i = blockIdx.x * blockDim.x + threadIdx.x;
    if (i >= BB * DXK) return;
    int b = i / DXK, c = i % DXK;
    x[i] = (c < EMBD) ? et[b * EMBD + c] : ctx[b * E2 + (c - EMBD)];
}

__global__ void concat_m_k(const float* __restrict__ h, const float* __restrict__ ctx,
                           const float* __restrict__ et, float* __restrict__ mi)
{
    int i = blockIdx.x * blockDim.x + threadIdx.x;
    if (i >= BB * MXK) return;
    int b = i / MXK, c = i % MXK;
    float v;
    if (c < HIDN)           v = h[b * HIDN + c];
    else if (c < HIDN + E2) v = ctx[b * E2 + (c - HIDN)];
    else                    v = et[b * EMBD + (c - HIDN - E2)];
    mi[i] = v;
}

__global__ void maxout_k(const float* __restrict__ t, float* __restrict__ tm)
{
    int i = blockIdx.x * blockDim.x + threadIdx.x;
    if (i >= BB * MXO) return;
    int b = i / MXO, o = i % MXO;
    tm[i] = fmaxf(t[b * MX2 + 2 * o], t[b * MX2 + 2 * o + 1]);
}

__global__ void argmax_k(const float* __restrict__ pred, int* __restrict__ inp)
{
    __shared__ float sv[256];
    __shared__ int   si[256];
    int b = blockIdx.x;
    const float* row = pred + (size_t)b * OUTV;
    float best = -1e30f; int bi = 0;
    for (int i = threadIdx.x; i < OUTV; i += 256) {
        float v = row[i];
        if (v > best) { best = v; bi = i; }
    }
    sv[threadIdx.x] = best; si[threadIdx.x] = bi;
    __syncthreads();
    for (int s = 128; s; s >>= 1) {
        if (threadIdx.x < s) {
            float ov = sv[threadIdx.x + s]; int oi = si[threadIdx.x + s];
            if (ov > sv[threadIdx.x] || (ov == sv[threadIdx.x] && oi < si[threadIdx.x])) {
                sv[threadIdx.x] = ov; si[threadIdx.x] = oi;
            }
        }
        __syncthreads();
    }
    if (threadIdx.x == 0) inp[b] = si[0];
}

// ---------------------------------------------------------------------------
// Host-side launch helpers
// ---------------------------------------------------------------------------
static inline void gemm(const float* A, int lda, const float* Bp, int ldb, int boff,
                        const float* bias, float* C, int M, int N, int K,
                        int split, int act)
{
    int kc = (K + split - 1) / split;
    dim3 grid((N + 63) / 64, (M + 63) / 64, split);
    gemm_nt_k<<<grid, 256>>>(A, lda, Bp, ldb, boff, bias, C, M, N, K, kc, act);
}

static inline int up(int n, int b) { return (n + b - 1) / b; }

extern "C" void kernel_launch(void* const* d_in, const int* in_sizes, int n_in,
                              void* d_out, int out_size)
{
    (void)in_sizes; (void)n_in; (void)out_size;
    const int*   src      = (const int*)  d_in[0];
    const int*   trg      = (const int*)  d_in[1];
    const float* enc_emb  = (const float*)d_in[2];
    const float* enc_wx_f = (const float*)d_in[3];
    const float* enc_wh_f = (const float*)d_in[4];
    const float* enc_bx_f = (const float*)d_in[5];
    const float* enc_bh_f = (const float*)d_in[6];
    const float* enc_wx_b = (const float*)d_in[7];
    const float* enc_wh_b = (const float*)d_in[8];
    const float* enc_bx_b = (const float*)d_in[9];
    const float* enc_bh_b = (const float*)d_in[10];
    const float* enc_fc_w = (const float*)d_in[11];
    const float* enc_fc_b = (const float*)d_in[12];
    const float* attn_w   = (const float*)d_in[13];
    const float* attn_b   = (const float*)d_in[14];
    const float* attn_v   = (const float*)d_in[15];
    const float* dec_emb  = (const float*)d_in[16];
    const float* dec_wx   = (const float*)d_in[17];
    const float* dec_wh   = (const float*)d_in[18];
    const float* dec_bx   = (const float*)d_in[19];
    const float* dec_bh   = (const float*)d_in[20];
    const float* max_w    = (const float*)d_in[21];
    const float* max_b    = (const float*)d_in[22];
    const float* out_w    = (const float*)d_in[23];
    const float* out_b    = (const float*)d_in[24];

    float* ws = nullptr;
    int* inp = nullptr;
    cudaGetSymbolAddress((void**)&ws, g_ws);
    cudaGetSymbolAddress((void**)&inp, g_inp);

    float* emb  = ws + O_EMB;
    float* gxf  = ws + O_GXF;
    float* gxb  = ws + O_GXB;
    float* enc  = ws + O_ENC;
    float* ep   = ws + O_EP;
    float* pa   = ws + O_PA;
    float* pb   = ws + O_PB;
    float* h    = ws + O_H;
    float* hd   = ws + O_HD;
    float* hq   = ws + O_HQ;
    float* sc   = ws + O_SC;
    float* al   = ws + O_AL;
    float* ctx  = ws + O_CTX;
    float* et   = ws + O_ET;
    float* x    = ws + O_X;
    float* mi   = ws + O_MI;
    float* tbuf = ws + O_T;
    float* tm   = ws + O_TM;
    float* out  = (float*)d_out;

    // output row 0 = zeros
    cudaMemsetAsync(out, 0, (size_t)BB * OUTV * sizeof(float));

    // ---------------- Encoder ----------------
    embed_k<<<up(S_LEN * BB * EMBD, 256), 256>>>(enc_emb, src, emb, S_LEN * BB, EMBD);
    // batched input-gate GEMMs for all timesteps, both directions
    gemm(emb, EMBD, enc_wx_f, EMBD, 0, enc_bx_f, gxf, S_LEN * BB, G3, EMBD, 1, 0);
    gemm(emb, EMBD, enc_wx_b, EMBD, 0, enc_bx_b, gxb, S_LEN * BB, G3, EMBD, 1, 0);

    cudaMemsetAsync(h, 0, (size_t)BB * HIDN * sizeof(float));
    for (int s = 0; s < S_LEN; s++) {
        gemm(h, HIDN, enc_wh_f, HIDN, 0, nullptr, pa, BB, G3, HIDN, 4, 0);
        gru_gate_k<<<up(BB * HIDN, 256), 256>>>(gxf + (size_t)s * BB * G3, 1, nullptr,
                                                pa, 4, enc_bh_f, h,
                                                enc + (size_t)s * BB * E2);
    }
    cudaMemsetAsync(h, 0, (size_t)BB * HIDN * sizeof(float));
    for (int s = S_LEN - 1; s >= 0; s--) {
        gemm(h, HIDN, enc_wh_b, HIDN, 0, nullptr, pa, BB, G3, HIDN, 4, 0);
        gru_gate_k<<<up(BB * HIDN, 256), 256>>>(gxb + (size_t)s * BB * G3, 1, nullptr,
                                                pa, 4, enc_bh_b, h,
                                                enc + (size_t)s * BB * E2 + HIDN);
    }
    // hidden = tanh(h_b @ enc_fc_w^T + b)
    gemm(h, HIDN, enc_fc_w, HIDN, 0, nullptr, pa, BB, HIDN, HIDN, 8, 0);
    finalize_k<<<up(BB * HIDN, 256), 256>>>(pa, 8, enc_fc_b, hd, BB * HIDN, HIDN, 1);
    // e_part = enc_out @ aw_e^T  (attn_w columns [HID:3HID])
    gemm(enc, E2, attn_w, G3, HIDN, nullptr, ep, S_LEN * BB, ATTD, E2, 1, 0);

    // ---------------- Decoder ----------------
    copy_inp_k<<<1, BB>>>(trg, inp);
    for (int t = 0; t < T_LEN - 1; t++) {
        embed_k<<<up(BB * EMBD, 256), 256>>>(dec_emb, inp, et, BB, EMBD);
        // hq = h @ aw_h^T  (attn_w columns [0:HID])
        gemm(hd, HIDN, attn_w, G3, 0, nullptr, pa, BB, ATTD, HIDN, 8, 0);
        finalize_k<<<up(BB * ATTD, 256), 256>>>(pa, 8, nullptr, hq, BB * ATTD, ATTD, 0);
        energy_k<<<(S_LEN * BB) / 8, 256>>>(hq, ep, attn_b, attn_v, sc);
        softmax_k<<<1, BB>>>(sc, al);
        ctx_k<<<up(BB * E2, 256), 256>>>(al, enc, ctx);
        concat_x_k<<<up(BB * DXK, 256), 256>>>(et, ctx, x);
        gemm(x, DXK, dec_wx, DXK, 0, nullptr, pa, BB, G3, DXK, 4, 0);
        gemm(hd, HIDN, dec_wh, HIDN, 0, nullptr, pb, BB, G3, HIDN, 4, 0);
        gru_gate_k<<<up(BB * HIDN, 256), 256>>>(pa, 4, dec_bx, pb, 4, dec_bh, hd, nullptr);
        concat_m_k<<<up(BB * MXK, 256), 256>>>(hd, ctx, et, mi);
        gemm(mi, MXK, max_w, MXK, 0, nullptr, pa, BB, MX2, MXK, 8, 0);
        finalize_k<<<up(BB * MX2, 256), 256>>>(pa, 8, max_b, tbuf, BB * MX2, MX2, 0);
        maxout_k<<<up(BB * MXO, 256), 256>>>(tbuf, tm);
        float* pred = out + (size_t)(t + 1) * BB * OUTV;
        gemm(tm, MXO, out_w, MXO, 0, out_b, pred, BB, OUTV, MXO, 1, 0);
        argmax_k<<<BB, 256>>>(pred, inp);
    }
}

// round 2
// speedup vs baseline: 1.2094x; 1.2094x over previous
#include <cuda_runtime.h>
#include <math.h>
#include <stdint.h>

// ---------------------------------------------------------------------------
// Problem constants
// ---------------------------------------------------------------------------
#define S_LEN 40
#define T_LEN 30
#define BB    64
#define EMBD  620
#define HIDN  1000
#define ATTD  1000
#define MXO   500
#define OUTV  30000
#define G3    3000            // 3*HID
#define E2    2000            // 2*HID
#define DXK   2620            // 2*HID + EMB
#define MXK   3620            // 3*HID + EMB
#define MX2   1000            // 2*MXO

// ---------------------------------------------------------------------------
// Workspace arena (device global; no cudaMalloc allowed)
// ---------------------------------------------------------------------------
static const size_t O_EMB = 0;                                   // S*B*EMB
static const size_t O_GXF = O_EMB + (size_t)S_LEN*BB*EMBD;       // S*B*G3
static const size_t O_GXB = O_GXF + (size_t)S_LEN*BB*G3;         // S*B*G3
static const size_t O_ENC = O_GXB + (size_t)S_LEN*BB*G3;         // S*B*E2
static const size_t O_EP  = O_ENC + (size_t)S_LEN*BB*E2;         // S*B*ATT
static const size_t O_PA  = O_EP  + (size_t)S_LEN*BB*ATTD;       // 16*B*G3 partials
static const size_t O_PB  = O_PA  + (size_t)16*BB*G3;            // 8*B*G3 partials
static const size_t O_PM  = O_PB  + (size_t)8*BB*G3;             // 16*B*MX2 partials
static const size_t O_PO  = O_PM  + (size_t)16*BB*MX2;           // 2*B*OUTV partials
static const size_t O_H   = O_PO  + (size_t)2*BB*OUTV;           // B*HID
static const size_t O_HD  = O_H   + (size_t)BB*HIDN;             // B*HID (decoder h)
static const size_t O_X   = O_HD  + (size_t)BB*HIDN;             // B*DXK
static const size_t O_MI  = O_X   + (size_t)BB*DXK;              // B*MXK
static const size_t O_TM  = O_MI  + (size_t)BB*MXK;              // B*MXO
static const size_t ARENA = O_TM  + (size_t)BB*MXO;

__device__ float g_ws[ARENA];
__device__ int   g_inp[BB];

// ---------------------------------------------------------------------------
// GEMM: C[M,N] = act(A[M,K(lda)] @ B[N,K]^T + bias)
// B element = Bp[n*ldb + boff + k]   (supports attn_w column slices)
// grid.z = split-K: partial z writes C + z*M*N (bias/act only when split==1)
// Tile 64(M) x 128(N) x 16(K); 256 threads; 4x8 micro-tile; register prefetch.
// Requirements: M % 64 == 0; lda,ldb,boff,kc multiples of 4 (kc mult of 16).
// ---------------------------------------------------------------------------
__global__ void __launch_bounds__(256) gemm_k(
    const float* __restrict__ A, int lda,
    const float* __restrict__ Bp, int ldb, int boff,
    const float* __restrict__ bias, float* __restrict__ C,
    int M, int N, int K, int kc, int act)
{
    __shared__ float As[16][65];
    __shared__ float Bs[16][128];

    const int n0 = blockIdx.x * 128;
    const int m0 = blockIdx.y * 64;
    const int z  = blockIdx.z;
    const int k0 = z * kc;
    int k1 = k0 + kc; if (k1 > K) k1 = K;
    float* Cz = C + (size_t)z * M * N;

    const int tid = threadIdx.x;
    const int tx = tid & 15;         // N micro index (8 cols)
    const int ty = tid >> 4;         // M micro index (4 rows)

    // loader coordinates
    const int am = m0 + (tid >> 2);          // A row
    const int ak = (tid & 3) * 4;            // A k-offset within tile
    const int bn = n0 + (tid >> 1);          // B row (output col)
    const int bk = (tid & 1) * 8;            // B k-offset within tile
    const bool bvalid = (bn < N);
    const float* Arow = A + (size_t)am * lda;
    const float* Brow = bvalid ? (Bp + (size_t)bn * ldb + boff) : Bp;

    float acc[4][8];
#pragma unroll
    for (int i = 0; i < 4; i++)
#pragma unroll
        for (int j = 0; j < 8; j++) acc[i][j] = 0.f;

    float ra[4], rb[8];

    // --- prefetch first tile ---
    if (k0 < k1) {
        int g = k0 + ak;
        if (g + 3 < k1) {
            float4 t = *(const float4*)(Arow + g);
            ra[0] = t.x; ra[1] = t.y; ra[2] = t.z; ra[3] = t.w;
        } else {
#pragma unroll
            for (int i = 0; i < 4; i++) ra[i] = (g + i < k1) ? Arow[g + i] : 0.f;
        }
        int gb = k0 + bk;
        if (!bvalid) {
#pragma unroll
            for (int i = 0; i < 8; i++) rb[i] = 0.f;
        } else if (gb + 7 < k1) {
            float4 t0 = *(const float4*)(Brow + gb);
            float4 t1 = *(const float4*)(Brow + gb + 4);
            rb[0] = t0.x; rb[1] = t0.y; rb[2] = t0.z; rb[3] = t0.w;
            rb[4] = t1.x; rb[5] = t1.y; rb[6] = t1.z; rb[7] = t1.w;
        } else {
#pragma unroll
            for (int i = 0; i < 8; i++) rb[i] = (gb + i < k1) ? Brow[gb + i] : 0.f;
        }
    }

    for (int kt = k0; kt < k1; kt += 16) {
        // store prefetched tile to smem (transposed)
#pragma unroll
        for (int i = 0; i < 4; i++) As[ak + i][tid >> 2] = ra[i];
#pragma unroll
        for (int i = 0; i < 8; i++) Bs[bk + i][tid >> 1] = rb[i];
        __syncthreads();

        // prefetch next tile
        int kn = kt + 16;
        if (kn < k1) {
            int g = kn + ak;
            if (g + 3 < k1) {
                float4 t = *(const float4*)(Arow + g);
                ra[0] = t.x; ra[1] = t.y; ra[2] = t.z; ra[3] = t.w;
            } else {
#pragma unroll
                for (int i = 0; i < 4; i++) ra[i] = (g + i < k1) ? Arow[g + i] : 0.f;
            }
            int gb = kn + bk;
            if (!bvalid) {
#pragma unroll
                for (int i = 0; i < 8; i++) rb[i] = 0.f;
            } else if (gb + 7 < k1) {
                float4 t0 = *(const float4*)(Brow + gb);
                float4 t1 = *(const float4*)(Brow + gb + 4);
                rb[0] = t0.x; rb[1] = t0.y; rb[2] = t0.z; rb[3] = t0.w;
                rb[4] = t1.x; rb[5] = t1.y; rb[6] = t1.z; rb[7] = t1.w;
            } else {
#pragma unroll
                for (int i = 0; i < 8; i++) rb[i] = (gb + i < k1) ? Brow[gb + i] : 0.f;
            }
        }

        // compute
#pragma unroll
        for (int kk = 0; kk < 16; kk++) {
            float a0 = As[kk][ty * 4 + 0];
            float a1 = As[kk][ty * 4 + 1];
            float a2 = As[kk][ty * 4 + 2];
            float a3 = As[kk][ty * 4 + 3];
            float4 b0 = *(const float4*)&Bs[kk][tx * 8];
            float4 b1 = *(const float4*)&Bs[kk][tx * 8 + 4];
            float bbv[8] = {b0.x, b0.y, b0.z, b0.w, b1.x, b1.y, b1.z, b1.w};
#pragma unroll
            for (int j = 0; j < 8; j++) {
                acc[0][j] += a0 * bbv[j];
                acc[1][j] += a1 * bbv[j];
                acc[2][j] += a2 * bbv[j];
                acc[3][j] += a3 * bbv[j];
            }
        }
        __syncthreads();
    }

    const bool fin = (gridDim.z == 1);
#pragma unroll
    for (int i = 0; i < 4; i++) {
        int r = m0 + ty * 4 + i;
        if (r >= M) continue;
#pragma unroll
        for (int j = 0; j < 8; j++) {
            int c = n0 + tx * 8 + j;
            if (c >= N) continue;
            float v = acc[i][j];
            if (fin) {
                if (bias) v += bias[c];
                if (act == 1) v = tanhf(v);
            }
            Cz[(size_t)r * N + c] = v;
        }
    }
}

// sum split-K partials + bias + optional tanh
__global__ void finalize_k(const float* __restrict__ parts, int nz,
                           const float* __restrict__ bias,
                           float* __restrict__ out, int MN, int N, int act)
{
    int i = blockIdx.x * blockDim.x + threadIdx.x;
    if (i >= MN) return;
    float v = 0.f;
    for (int z = 0; z < nz; z++) v += parts[(size_t)z * MN + i];
    if (bias) v += bias[i % N];
    if (act) v = tanhf(v);
    out[i] = v;
}

// sum split-K partials of maxout GEMM + bias, then pairwise max -> tm[B,MXO]
__global__ void finalize_max_k(const float* __restrict__ pm, int nz,
                               const float* __restrict__ bias,
                               float* __restrict__ tm)
{
    int i = blockIdx.x * blockDim.x + threadIdx.x;
    if (i >= BB * MXO) return;
    int b = i / MXO, o = i % MXO;
    float v0 = bias[2 * o], v1 = bias[2 * o + 1];
    for (int z = 0; z < nz; z++) {
        const float* p = pm + ((size_t)z * BB + b) * MX2;
        v0 += p[2 * o];
        v1 += p[2 * o + 1];
    }
    tm[i] = fmaxf(v0, v1);
}

// GRU gate. gx/gh are zx/zh stacked partial [B,G3] buffers (stride BB*G3).
// h updated in place; optionally also written to eout[b*estride + j].
__global__ void gru_gate_k(const float* __restrict__ gx, int zx, const float* __restrict__ bx,
                           const float* __restrict__ gh, int zh, const float* __restrict__ bh,
                           float* __restrict__ h, float* __restrict__ eout, int estride)
{
    int i = blockIdx.x * blockDim.x + threadIdx.x;
    if (i >= BB * HIDN) return;
    int b = i / HIDN, j = i % HIDN;
    float xr = 0.f, xz = 0.f, xn = 0.f, hr = 0.f, hz = 0.f, hn = 0.f;
    for (int z = 0; z < zx; z++) {
        const float* p = gx + ((size_t)z * BB + b) * G3;
        xr += p[j]; xz += p[HIDN + j]; xn += p[2 * HIDN + j];
    }
    if (bx) { xr += bx[j]; xz += bx[HIDN + j]; xn += bx[2 * HIDN + j]; }
    for (int z = 0; z < zh; z++) {
        const float* p = gh + ((size_t)z * BB + b) * G3;
        hr += p[j]; hz += p[HIDN + j]; hn += p[2 * HIDN + j];
    }
    hr += bh[j]; hz += bh[HIDN + j]; hn += bh[2 * HIDN + j];
    float r  = 1.f / (1.f + expf(-(xr + hr)));
    float zz = 1.f / (1.f + expf(-(xz + hz)));
    float n  = tanhf(xn + r * hn);
    float h2 = (1.f - zz) * n + zz * h[i];
    h[i] = h2;
    if (eout) eout[(size_t)b * estride + j] = h2;
}

__global__ void embed_k(const float* __restrict__ table, const int* __restrict__ idx,
                        float* __restrict__ out, int rows, int E)
{
    int i = blockIdx.x * blockDim.x + threadIdx.x;
    if (i >= rows * E) return;
    int r = i / E, e = i % E;
    out[i] = table[(size_t)idx[r] * E + e];
}

__global__ void copy_inp_k(const int* __restrict__ trg, int* __restrict__ inp)
{
    inp[threadIdx.x] = trg[threadIdx.x];
}

// Fused per-step attention: hq partial-sum + energy + softmax + context +
// decoder-embedding gather. Builds GRU input x=[emb|ctx] and maxout input
// mi[:, HIDN:] = [ctx|emb] (mi[:, :HIDN] filled later by gru_gate).
// One block per batch element b, 256 threads.
__global__ void attention_k(const float* __restrict__ pa,   // 8 partials of hq [B,ATT]
                            const float* __restrict__ ep,   // [S,B,ATT]
                            const float* __restrict__ ab,   // attn_b [ATT]
                            const float* __restrict__ av,   // attn_v [ATT]
                            const float* __restrict__ enc,  // [S,B,E2]
                            const float* __restrict__ demb, // dec_emb [OUTV,EMB]
                            const int*   __restrict__ inp,  // [B]
                            float* __restrict__ x,          // [B,DXK]
                            float* __restrict__ mi)         // [B,MXK]
{
    const int b = blockIdx.x;
    const int tid = threadIdx.x;
    __shared__ float hqs[ATTD];
    __shared__ float al[S_LEN];
    __shared__ float red[8];

    for (int a = tid; a < ATTD; a += 256) {
        float s = 0.f;
#pragma unroll
        for (int z = 0; z < 8; z++) s += pa[((size_t)z * BB + b) * ATTD + a];
        hqs[a] = s;
    }
    __syncthreads();

    for (int s = 0; s < S_LEN; s++) {
        const float* eprow = ep + ((size_t)s * BB + b) * ATTD;
        float e = 0.f;
        for (int a = tid; a < ATTD; a += 256)
            e += av[a] * tanhf(hqs[a] + eprow[a] + ab[a]);
#pragma unroll
        for (int o = 16; o; o >>= 1) e += __shfl_down_sync(0xffffffffu, e, o);
        if ((tid & 31) == 0) red[tid >> 5] = e;
        __syncthreads();
        if (tid == 0) {
            float t = 0.f;
            for (int w = 0; w < 8; w++) t += red[w];
            al[s] = t;
        }
        __syncthreads();
    }

    if (tid == 0) {
        float m = -1e30f;
        for (int s = 0; s < S_LEN; s++) m = fmaxf(m, al[s]);
        float sum = 0.f;
        for (int s = 0; s < S_LEN; s++) { float e = expf(al[s] - m); al[s] = e; sum += e; }
        float inv = 1.f / sum;
        for (int s = 0; s < S_LEN; s++) al[s] *= inv;
    }
    __syncthreads();

    // context -> x[:, EMBD:] and mi[:, HIDN:HIDN+E2]
    for (int hc = tid; hc < E2; hc += 256) {
        float c = 0.f;
        for (int s = 0; s < S_LEN; s++)
            c += al[s] * enc[((size_t)s * BB + b) * E2 + hc];
        x [(size_t)b * DXK + EMBD + hc] = c;
        mi[(size_t)b * MXK + HIDN + hc] = c;
    }
    // embedding -> x[:, :EMBD] and mi[:, G3:]
    const int tok = inp[b];
    for (int e = tid; e < EMBD; e += 256) {
        float vv = demb[(size_t)tok * EMBD + e];
        x [(size_t)b * DXK + e] = vv;
        mi[(size_t)b * MXK + G3 + e] = vv;
    }
}

__global__ void argmax_k(const float* __restrict__ pred, int* __restrict__ inp)
{
    __shared__ float sv[256];
    __shared__ int   si[256];
    int b = blockIdx.x;
    const float* row = pred + (size_t)b * OUTV;
    float best = -1e30f; int bi = 0;
    for (int i = threadIdx.x; i < OUTV; i += 256) {
        float v = row[i];
        if (v > best) { best = v; bi = i; }
    }
    sv[threadIdx.x] = best; si[threadIdx.x] = bi;
    __syncthreads();
    for (int s = 128; s; s >>= 1) {
        if (threadIdx.x < s) {
            float ov = sv[threadIdx.x + s]; int oi = si[threadIdx.x + s];
            if (ov > sv[threadIdx.x] || (ov == sv[threadIdx.x] && oi < si[threadIdx.x])) {
                sv[threadIdx.x] = ov; si[threadIdx.x] = oi;
            }
        }
        __syncthreads();
    }
    if (threadIdx.x == 0) inp[b] = si[0];
}

// ---------------------------------------------------------------------------
// Host-side launch helpers
// ---------------------------------------------------------------------------
static inline int up(int n, int b) { return (n + b - 1) / b; }

static inline void gemm(const float* A, int lda, const float* Bp, int ldb, int boff,
                        const float* bias, float* C, int M, int N, int K,
                        int split, int act)
{
    int kc = ((K + split - 1) / split + 15) & ~15;   // multiple of 16
    dim3 grid(up(N, 128), up(M, 64), split);
    gemm_k<<<grid, 256>>>(A, lda, Bp, ldb, boff, bias, C, M, N, K, kc, act);
}

extern "C" void kernel_launch(void* const* d_in, const int* in_sizes, int n_in,
                              void* d_out, int out_size)
{
    (void)in_sizes; (void)n_in; (void)out_size;
    const int*   src      = (const int*)  d_in[0];
    const int*   trg      = (const int*)  d_in[1];
    const float* enc_emb  = (const float*)d_in[2];
    const float* enc_wx_f = (const float*)d_in[3];
    const float* enc_wh_f = (const float*)d_in[4];
    const float* enc_bx_f = (const float*)d_in[5];
    const float* enc_bh_f = (const float*)d_in[6];
    const float* enc_wx_b = (const float*)d_in[7];
    const float* enc_wh_b = (const float*)d_in[8];
    const float* enc_bx_b = (const float*)d_in[9];
    const float* enc_bh_b = (const float*)d_in[10];
    const float* enc_fc_w = (const float*)d_in[11];
    const float* enc_fc_b = (const float*)d_in[12];
    const float* attn_w   = (const float*)d_in[13];
    const float* attn_b   = (const float*)d_in[14];
    const float* attn_v   = (const float*)d_in[15];
    const float* dec_emb  = (const float*)d_in[16];
    const float* dec_wx   = (const float*)d_in[17];
    const float* dec_wh   = (const float*)d_in[18];
    const float* dec_bx   = (const float*)d_in[19];
    const float* dec_bh   = (const float*)d_in[20];
    const float* max_w    = (const float*)d_in[21];
    const float* max_b    = (const float*)d_in[22];
    const float* out_w    = (const float*)d_in[23];
    const float* out_b    = (const float*)d_in[24];

    float* ws = nullptr;
    int* inp = nullptr;
    cudaGetSymbolAddress((void**)&ws, g_ws);
    cudaGetSymbolAddress((void**)&inp, g_inp);

    float* emb  = ws + O_EMB;
    float* gxf  = ws + O_GXF;
    float* gxb  = ws + O_GXB;
    float* enc  = ws + O_ENC;
    float* ep   = ws + O_EP;
    float* pa   = ws + O_PA;
    float* pb   = ws + O_PB;
    float* pm   = ws + O_PM;
    float* po   = ws + O_PO;
    float* h    = ws + O_H;
    float* hd   = ws + O_HD;
    float* x    = ws + O_X;
    float* mi   = ws + O_MI;
    float* tm   = ws + O_TM;
    float* out  = (float*)d_out;

    // output row 0 = zeros
    cudaMemsetAsync(out, 0, (size_t)BB * OUTV * sizeof(float));

    // ---------------- Encoder ----------------
    embed_k<<<up(S_LEN * BB * EMBD, 256), 256>>>(enc_emb, src, emb, S_LEN * BB, EMBD);
    gemm(emb, EMBD, enc_wx_f, EMBD, 0, enc_bx_f, gxf, S_LEN * BB, G3, EMBD, 1, 0);
    gemm(emb, EMBD, enc_wx_b, EMBD, 0, enc_bx_b, gxb, S_LEN * BB, G3, EMBD, 1, 0);

    cudaMemsetAsync(h, 0, (size_t)BB * HIDN * sizeof(float));
    for (int s = 0; s < S_LEN; s++) {
        gemm(h, HIDN, enc_wh_f, HIDN, 0, nullptr, pa, BB, G3, HIDN, 8, 0);
        gru_gate_k<<<up(BB * HIDN, 256), 256>>>(gxf + (size_t)s * BB * G3, 1, nullptr,
                                                pa, 8, enc_bh_f, h,
                                                enc + (size_t)s * BB * E2, E2);
    }
    cudaMemsetAsync(h, 0, (size_t)BB * HIDN * sizeof(float));
    for (int s = S_LEN - 1; s >= 0; s--) {
        gemm(h, HIDN, enc_wh_b, HIDN, 0, nullptr, pa, BB, G3, HIDN, 8, 0);
        gru_gate_k<<<up(BB * HIDN, 256), 256>>>(gxb + (size_t)s * BB * G3, 1, nullptr,
                                                pa, 8, enc_bh_b, h,
                                                enc + (size_t)s * BB * E2 + HIDN, E2);
    }
    // hidden = tanh(h_b @ enc_fc_w^T + b)
    gemm(h, HIDN, enc_fc_w, HIDN, 0, nullptr, pa, BB, HIDN, HIDN, 8, 0);
    finalize_k<<<up(BB * HIDN, 256), 256>>>(pa, 8, enc_fc_b, hd, BB * HIDN, HIDN, 1);
    // e_part = enc_out @ aw_e^T  (attn_w columns [HID:3HID])
    gemm(enc, E2, attn_w, G3, HIDN, nullptr, ep, S_LEN * BB, ATTD, E2, 1, 0);

    // ---------------- Decoder ----------------
    copy_inp_k<<<1, BB>>>(trg, inp);
    for (int t = 0; t < T_LEN - 1; t++) {
        // hq partials = hd @ aw_h^T  (attn_w columns [0:HID])
        gemm(hd, HIDN, attn_w, G3, 0, nullptr, pa, BB, ATTD, HIDN, 8, 0);
        attention_k<<<BB, 256>>>(pa, ep, attn_b, attn_v, enc, dec_emb, inp, x, mi);
        gemm(x,  DXK,  dec_wx, DXK,  0, nullptr, pa, BB, G3, DXK,  8, 0);
        gemm(hd, HIDN, dec_wh, HIDN, 0, nullptr, pb, BB, G3, HIDN, 8, 0);
        gru_gate_k<<<up(BB * HIDN, 256), 256>>>(pa, 8, dec_bx, pb, 8, dec_bh, hd, mi, MXK);
        gemm(mi, MXK, max_w, MXK, 0, nullptr, pm, BB, MX2, MXK, 16, 0);
        finalize_max_k<<<up(BB * MXO, 256), 256>>>(pm, 16, max_b, tm);
        float* pred = out + (size_t)(t + 1) * BB * OUTV;
        gemm(tm, MXO, out_w, MXO, 0, nullptr, po, BB, OUTV, MXO, 2, 0);
        finalize_k<<<up(BB * OUTV, 256), 256>>>(po, 2, out_b, pred, BB * OUTV, OUTV, 0);
        argmax_k<<<BB, 256>>>(pred, inp);
    }
}

// round 3
// speedup vs baseline: 1.5186x; 1.2557x over previous
#include <cuda_runtime.h>
#include <math.h>
#include <stdint.h>

// ---------------------------------------------------------------------------
// Problem constants
// ---------------------------------------------------------------------------
#define S_LEN 40
#define T_LEN 30
#define BB    64
#define EMBD  620
#define HIDN  1000
#define ATTD  1000
#define MXO   500
#define OUTV  30000
#define G3    3000            // 3*HID
#define E2    2000            // 2*HID
#define DXK   2620            // 2*HID + EMB
#define MXK   3620            // 3*HID + EMB
#define MX2   1000            // 2*MXO

// ---------------------------------------------------------------------------
// Workspace arena (device global; no cudaMalloc allowed)
// ---------------------------------------------------------------------------
static const size_t O_EMB = 0;                                   // S*B*EMB
static const size_t O_GXF = O_EMB + (size_t)S_LEN*BB*EMBD;       // S*B*G3
static const size_t O_GXB = O_GXF + (size_t)S_LEN*BB*G3;         // S*B*G3
static const size_t O_ENC = O_GXB + (size_t)S_LEN*BB*G3;         // S*B*E2
static const size_t O_EP  = O_ENC + (size_t)S_LEN*BB*E2;         // S*B*ATT
static const size_t O_PA  = O_EP  + (size_t)S_LEN*BB*ATTD;       // 16*B*G3 partials
static const size_t O_PB  = O_PA  + (size_t)16*BB*G3;            // 8*B*G3 partials
static const size_t O_PM  = O_PB  + (size_t)8*BB*G3;             // 16*B*MX2 partials
static const size_t O_HF  = O_PM  + (size_t)16*BB*MX2;           // B*HID fwd
static const size_t O_HB  = O_HF  + (size_t)BB*HIDN;             // B*HID bwd
static const size_t O_HD  = O_HB  + (size_t)BB*HIDN;             // B*HID decoder
static const size_t O_X   = O_HD  + (size_t)BB*HIDN;             // B*DXK
static const size_t O_MI  = O_X   + (size_t)BB*DXK;              // B*MXK
static const size_t O_TM  = O_MI  + (size_t)BB*MXK;              // B*MXO
static const size_t ARENA = O_TM  + (size_t)BB*MXO;

__device__ __align__(256) float g_ws[ARENA];
__device__ int g_inp[BB];

// ---------------------------------------------------------------------------
// packed f32x2 FMA
// ---------------------------------------------------------------------------
__device__ __forceinline__ void ffma2(unsigned long long& d,
                                      unsigned long long a,
                                      unsigned long long b)
{
    asm("fma.rn.f32x2 %0, %1, %2, %0;" : "+l"(d) : "l"(a), "l"(b));
}

// guarded 8-float load starting at p+g, valid range [.., k1)
__device__ __forceinline__ void ld8(const float* __restrict__ p, int g, int k1,
                                    float* r)
{
    if (g + 7 < k1) {
        float4 t0 = *(const float4*)(p + g);
        float4 t1 = *(const float4*)(p + g + 4);
        r[0] = t0.x; r[1] = t0.y; r[2] = t0.z; r[3] = t0.w;
        r[4] = t1.x; r[5] = t1.y; r[6] = t1.z; r[7] = t1.w;
    } else {
#pragma unroll
        for (int i = 0; i < 8; i++) r[i] = (g + i < k1) ? p[g + i] : 0.f;
    }
}

struct GArgs {
    const float* A;     // [M, lda]
    const float* B;     // [N, ldb], element B[n*ldb + boff + k]
    const float* bias;  // [N] or null (applied only when gridDim.z==1)
    float* C;           // split z writes C + z*M*N
    int lda, ldb, boff, M, N, K, kc;
};

// ---------------------------------------------------------------------------
// GEMM: C = A @ B^T (+bias when single split).
// Tile 64(M) x 128(N) x 16(K), 128 threads, 8x8 micro-tile, fma.rn.f32x2.
// dual=1: blockIdx.y selects arg set (M must be 64); dual=0: blockIdx.y = M tile.
// Requires lda/ldb/boff multiples of 4, kc multiple of 16, M multiple of 64.
// ---------------------------------------------------------------------------
__global__ void __launch_bounds__(128) gemm_k(GArgs g0, GArgs g1, int dual)
{
    const GArgs g = (dual && blockIdx.y) ? g1 : g0;
    const int m0 = dual ? 0 : blockIdx.y * 64;
    const int n0 = blockIdx.x * 128;
    const int z  = blockIdx.z;
    const int k0 = z * g.kc;
    int k1 = k0 + g.kc; if (k1 > g.K) k1 = g.K;

    __shared__ float As2[16][132];   // A pre-splatted: col 2m, 2m+1 hold same a
    __shared__ float Bs[16][132];

    const int tid = threadIdx.x;
    const int tx = tid & 15;         // 16 N positions (8 cols each)
    const int ty = tid >> 4;         // 8 M positions (8 rows each)

    const int arow = tid >> 1;           // A tile row 0..63
    const int ak   = (tid & 1) * 8;      // A k offset
    const int brow = tid;                // B tile row (output col) 0..127
    const bool bvalid = (n0 + brow) < g.N;
    const float* Ar = g.A + (size_t)(m0 + arow) * g.lda;
    const float* Br = bvalid ? (g.B + (size_t)(n0 + brow) * g.ldb + g.boff) : g.B;

    unsigned long long acc[8][4];
#pragma unroll
    for (int i = 0; i < 8; i++)
#pragma unroll
        for (int j = 0; j < 4; j++) acc[i][j] = 0ull;

    float ra[8], rb[16];
    if (k0 < k1) {
        ld8(Ar, k0 + ak, k1, ra);
        if (bvalid) { ld8(Br, k0, k1, rb); ld8(Br, k0 + 8, k1, rb + 8); }
        else {
#pragma unroll
            for (int i = 0; i < 16; i++) rb[i] = 0.f;
        }
    }

    for (int kt = k0; kt < k1; kt += 16) {
#pragma unroll
        for (int i = 0; i < 8; i++)
            *(float2*)&As2[ak + i][arow * 2] = make_float2(ra[i], ra[i]);
#pragma unroll
        for (int i = 0; i < 16; i++) Bs[i][brow] = rb[i];
        __syncthreads();

        int kn = kt + 16;
        if (kn < k1) {
            ld8(Ar, kn + ak, k1, ra);
            if (bvalid) { ld8(Br, kn, k1, rb); ld8(Br, kn + 8, k1, rb + 8); }
        }

#pragma unroll
        for (int kk = 0; kk < 16; kk++) {
            ulonglong2 a0 = *(const ulonglong2*)&As2[kk][ty * 16 + 0];
            ulonglong2 a1 = *(const ulonglong2*)&As2[kk][ty * 16 + 4];
            ulonglong2 a2 = *(const ulonglong2*)&As2[kk][ty * 16 + 8];
            ulonglong2 a3 = *(const ulonglong2*)&As2[kk][ty * 16 + 12];
            ulonglong2 b0 = *(const ulonglong2*)&Bs[kk][tx * 8 + 0];
            ulonglong2 b1 = *(const ulonglong2*)&Bs[kk][tx * 8 + 4];
            unsigned long long aa[8] = {a0.x, a0.y, a1.x, a1.y,
                                        a2.x, a2.y, a3.x, a3.y};
            unsigned long long bb[4] = {b0.x, b0.y, b1.x, b1.y};
#pragma unroll
            for (int i = 0; i < 8; i++) {
                ffma2(acc[i][0], aa[i], bb[0]);
                ffma2(acc[i][1], aa[i], bb[1]);
                ffma2(acc[i][2], aa[i], bb[2]);
                ffma2(acc[i][3], aa[i], bb[3]);
            }
        }
        __syncthreads();
    }

    const bool fin = (gridDim.z == 1);
    float* Cz = g.C + (size_t)z * g.M * g.N;
#pragma unroll
    for (int i = 0; i < 8; i++) {
        int r = m0 + ty * 8 + i;
#pragma unroll
        for (int j = 0; j < 4; j++) {
            union { unsigned long long u; float2 f; } v;
            v.u = acc[i][j];
            int c0 = n0 + tx * 8 + j * 2;
            if (c0 < g.N) {
                float x0 = v.f.x;
                if (fin && g.bias) x0 += g.bias[c0];
                Cz[(size_t)r * g.N + c0] = x0;
            }
            if (c0 + 1 < g.N) {
                float x1 = v.f.y;
                if (fin && g.bias) x1 += g.bias[c0 + 1];
                Cz[(size_t)r * g.N + c0 + 1] = x1;
            }
        }
    }
}

// sum split-K partials + bias + optional tanh
__global__ void finalize_k(const float* __restrict__ parts, int nz,
                           const float* __restrict__ bias,
                           float* __restrict__ out, int MN, int N, int act)
{
    int i = blockIdx.x * blockDim.x + threadIdx.x;
    if (i >= MN) return;
    float v = 0.f;
    for (int z = 0; z < nz; z++) v += parts[(size_t)z * MN + i];
    if (bias) v += bias[i % N];
    if (act) v = tanhf(v);
    out[i] = v;
}

// sum split-K partials of maxout GEMM + bias, pairwise max -> tm[B,MXO]
__global__ void finalize_max_k(const float* __restrict__ pm, int nz,
                               const float* __restrict__ bias,
                               float* __restrict__ tm)
{
    int i = blockIdx.x * blockDim.x + threadIdx.x;
    if (i >= BB * MXO) return;
    int b = i / MXO, o = i % MXO;
    float v0 = bias[2 * o], v1 = bias[2 * o + 1];
    for (int z = 0; z < nz; z++) {
        const float* p = pm + ((size_t)z * BB + b) * MX2;
        v0 += p[2 * o];
        v1 += p[2 * o + 1];
    }
    tm[i] = fmaxf(v0, v1);
}

// Decoder GRU gate: gx/gh zx/zh stacked partials [B,G3]; h in place;
// optional eout[b*estride + j] = h2.
__global__ void gru_gate_k(const float* __restrict__ gx, int zx, const float* __restrict__ bx,
                           const float* __restrict__ gh, int zh, const float* __restrict__ bh,
                           float* __restrict__ h, float* __restrict__ eout, int estride)
{
    int i = blockIdx.x * blockDim.x + threadIdx.x;
    if (i >= BB * HIDN) return;
    int b = i / HIDN, j = i % HIDN;
    float xr = 0.f, xz = 0.f, xn = 0.f, hr = 0.f, hz = 0.f, hn = 0.f;
    for (int z = 0; z < zx; z++) {
        const float* p = gx + ((size_t)z * BB + b) * G3;
        xr += p[j]; xz += p[HIDN + j]; xn += p[2 * HIDN + j];
    }
    if (bx) { xr += bx[j]; xz += bx[HIDN + j]; xn += bx[2 * HIDN + j]; }
    for (int z = 0; z < zh; z++) {
        const float* p = gh + ((size_t)z * BB + b) * G3;
        hr += p[j]; hz += p[HIDN + j]; hn += p[2 * HIDN + j];
    }
    hr += bh[j]; hz += bh[HIDN + j]; hn += bh[2 * HIDN + j];
    float r  = 1.f / (1.f + expf(-(xr + hr)));
    float zz = 1.f / (1.f + expf(-(xz + hz)));
    float n  = tanhf(xn + r * hn);
    float h2 = (1.f - zz) * n + zz * h[i];
    h[i] = h2;
    if (eout) eout[(size_t)b * estride + j] = h2;
}

// Paired encoder GRU gate: fwd (dir 0) and bwd (dir 1) in one launch.
// gx buffers already contain input bias. nz partials each from pf/pb.
__global__ void gru_gate2_k(const float* __restrict__ gxf, const float* __restrict__ gxb,
                            const float* __restrict__ pf, const float* __restrict__ pb,
                            int nz,
                            const float* __restrict__ bhf, const float* __restrict__ bhb,
                            float* __restrict__ hf, float* __restrict__ hb,
                            float* __restrict__ ef, float* __restrict__ eb)
{
    int i = blockIdx.x * blockDim.x + threadIdx.x;
    if (i >= 2 * BB * HIDN) return;
    int dir = (i >= BB * HIDN);
    int ii = dir ? i - BB * HIDN : i;
    int b = ii / HIDN, j = ii % HIDN;
    const float* gx = dir ? gxb : gxf;
    const float* ph = dir ? pb : pf;
    const float* bh = dir ? bhb : bhf;
    float* h  = dir ? hb : hf;
    float* eo = dir ? eb : ef;

    const float* q = gx + (size_t)b * G3;
    float xr = q[j], xz = q[HIDN + j], xn = q[2 * HIDN + j];
    float hr = bh[j], hz = bh[HIDN + j], hn = bh[2 * HIDN + j];
    for (int z = 0; z < nz; z++) {
        const float* p = ph + ((size_t)z * BB + b) * G3;
        hr += p[j]; hz += p[HIDN + j]; hn += p[2 * HIDN + j];
    }
    float r  = 1.f / (1.f + expf(-(xr + hr)));
    float zz = 1.f / (1.f + expf(-(xz + hz)));
    float n  = tanhf(xn + r * hn);
    float h2 = (1.f - zz) * n + zz * h[ii];
    h[ii] = h2;
    eo[(size_t)b * E2 + j] = h2;
}

__global__ void embed_k(const float* __restrict__ table, const int* __restrict__ idx,
                        float* __restrict__ out, int rows, int E)
{
    int i = blockIdx.x * blockDim.x + threadIdx.x;
    if (i >= rows * E) return;
    int r = i / E, e = i % E;
    out[i] = table[(size_t)idx[r] * E + e];
}

__global__ void copy_inp_k(const int* __restrict__ trg, int* __restrict__ inp)
{
    inp[threadIdx.x] = trg[threadIdx.x];
}

// Fused per-step attention: hq partial-sum + energy + softmax + context +
// decoder-embedding gather. Fills x=[emb|ctx] and mi[:, HIDN:]=[ctx|emb].
__global__ void attention_k(const float* __restrict__ pa,   // 8 hq partials [B,ATT]
                            const float* __restrict__ ep,   // [S,B,ATT]
                            const float* __restrict__ ab,
                            const float* __restrict__ av,
                            const float* __restrict__ enc,  // [S,B,E2]
                            const float* __restrict__ demb,
                            const int*   __restrict__ inp,
                            float* __restrict__ x,          // [B,DXK]
                            float* __restrict__ mi)         // [B,MXK]
{
    const int b = blockIdx.x;
    const int tid = threadIdx.x;
    __shared__ float hqs[ATTD];
    __shared__ float al[S_LEN];
    __shared__ float red[8];

    for (int a = tid; a < ATTD; a += 256) {
        float s = 0.f;
#pragma unroll
        for (int z = 0; z < 8; z++) s += pa[((size_t)z * BB + b) * ATTD + a];
        hqs[a] = s;
    }
    __syncthreads();

    for (int s = 0; s < S_LEN; s++) {
        const float* eprow = ep + ((size_t)s * BB + b) * ATTD;
        float e = 0.f;
        for (int a = tid; a < ATTD; a += 256)
            e += av[a] * tanhf(hqs[a] + eprow[a] + ab[a]);
#pragma unroll
        for (int o = 16; o; o >>= 1) e += __shfl_down_sync(0xffffffffu, e, o);
        if ((tid & 31) == 0) red[tid >> 5] = e;
        __syncthreads();
        if (tid == 0) {
            float t = 0.f;
            for (int w = 0; w < 8; w++) t += red[w];
            al[s] = t;
        }
        __syncthreads();
    }

    if (tid == 0) {
        float m = -1e30f;
        for (int s = 0; s < S_LEN; s++) m = fmaxf(m, al[s]);
        float sum = 0.f;
        for (int s = 0; s < S_LEN; s++) { float e = expf(al[s] - m); al[s] = e; sum += e; }
        float inv = 1.f / sum;
        for (int s = 0; s < S_LEN; s++) al[s] *= inv;
    }
    __syncthreads();

    for (int hc = tid; hc < E2; hc += 256) {
        float c = 0.f;
        for (int s = 0; s < S_LEN; s++)
            c += al[s] * enc[((size_t)s * BB + b) * E2 + hc];
        x [(size_t)b * DXK + EMBD + hc] = c;
        mi[(size_t)b * MXK + HIDN + hc] = c;
    }
    const int tok = inp[b];
    for (int e = tid; e < EMBD; e += 256) {
        float vv = demb[(size_t)tok * EMBD + e];
        x [(size_t)b * DXK + e] = vv;
        mi[(size_t)b * MXK + G3 + e] = vv;
    }
}

__global__ void argmax_k(const float* __restrict__ pred, int* __restrict__ inp)
{
    __shared__ float sv[256];
    __shared__ int   si[256];
    int b = blockIdx.x;
    const float* row = pred + (size_t)b * OUTV;
    float best = -1e30f; int bi = 0;
    for (int i = threadIdx.x; i < OUTV; i += 256) {
        float v = row[i];
        if (v > best) { best = v; bi = i; }
    }
    sv[threadIdx.x] = best; si[threadIdx.x] = bi;
    __syncthreads();
    for (int s = 128; s; s >>= 1) {
        if (threadIdx.x < s) {
            float ov = sv[threadIdx.x + s]; int oi = si[threadIdx.x + s];
            if (ov > sv[threadIdx.x] || (ov == sv[threadIdx.x] && oi < si[threadIdx.x])) {
                sv[threadIdx.x] = ov; si[threadIdx.x] = oi;
            }
        }
        __syncthreads();
    }
    if (threadIdx.x == 0) inp[b] = si[0];
}

// ---------------------------------------------------------------------------
// Host-side helpers
// ---------------------------------------------------------------------------
static inline int up(int n, int b) { return (n + b - 1) / b; }

static inline GArgs mk(const float* A, int lda, const float* B, int ldb, int boff,
                       const float* bias, float* C, int M, int N, int K, int split)
{
    GArgs g;
    g.A = A; g.B = B; g.bias = bias; g.C = C;
    g.lda = lda; g.ldb = ldb; g.boff = boff;
    g.M = M; g.N = N; g.K = K;
    g.kc = ((K + split - 1) / split + 15) & ~15;
    return g;
}

static inline void gemm1(const GArgs& g, int split)
{
    dim3 grid(up(g.N, 128), up(g.M, 64), split);
    gemm_k<<<grid, 128>>>(g, g, 0);
}

static inline void gemm2(const GArgs& a, const GArgs& b, int split)
{
    dim3 grid(up(a.N, 128), 2, split);   // a.N == b.N required
    gemm_k<<<grid, 128>>>(a, b, 1);
}

extern "C" void kernel_launch(void* const* d_in, const int* in_sizes, int n_in,
                              void* d_out, int out_size)
{
    (void)in_sizes; (void)n_in; (void)out_size;
    const int*   src      = (const int*)  d_in[0];
    const int*   trg      = (const int*)  d_in[1];
    const float* enc_emb  = (const float*)d_in[2];
    const float* enc_wx_f = (const float*)d_in[3];
    const float* enc_wh_f = (const float*)d_in[4];
    const float* enc_bx_f = (const float*)d_in[5];
    const float* enc_bh_f = (const float*)d_in[6];
    const float* enc_wx_b = (const float*)d_in[7];
    const float* enc_wh_b = (const float*)d_in[8];
    const float* enc_bx_b = (const float*)d_in[9];
    const float* enc_bh_b = (const float*)d_in[10];
    const float* enc_fc_w = (const float*)d_in[11];
    const float* enc_fc_b = (const float*)d_in[12];
    const float* attn_w   = (const float*)d_in[13];
    const float* attn_b   = (const float*)d_in[14];
    const float* attn_v   = (const float*)d_in[15];
    const float* dec_emb  = (const float*)d_in[16];
    const float* dec_wx   = (const float*)d_in[17];
    const float* dec_wh   = (const float*)d_in[18];
    const float* dec_bx   = (const float*)d_in[19];
    const float* dec_bh   = (const float*)d_in[20];
    const float* max_w    = (const float*)d_in[21];
    const float* max_b    = (const float*)d_in[22];
    const float* out_w    = (const float*)d_in[23];
    const float* out_b    = (const float*)d_in[24];

    float* ws = nullptr;
    int* inp = nullptr;
    cudaGetSymbolAddress((void**)&ws, g_ws);
    cudaGetSymbolAddress((void**)&inp, g_inp);

    float* emb = ws + O_EMB;
    float* gxf = ws + O_GXF;
    float* gxb = ws + O_GXB;
    float* enc = ws + O_ENC;
    float* ep  = ws + O_EP;
    float* pa  = ws + O_PA;
    float* pb  = ws + O_PB;
    float* pm  = ws + O_PM;
    float* hf  = ws + O_HF;
    float* hb  = ws + O_HB;
    float* hd  = ws + O_HD;
    float* x   = ws + O_X;
    float* mi  = ws + O_MI;
    float* tm  = ws + O_TM;
    float* out = (float*)d_out;

    cudaMemsetAsync(out, 0, (size_t)BB * OUTV * sizeof(float));

    // ---------------- Encoder ----------------
    embed_k<<<up(S_LEN * BB * EMBD, 256), 256>>>(enc_emb, src, emb, S_LEN * BB, EMBD);
    gemm1(mk(emb, EMBD, enc_wx_f, EMBD, 0, enc_bx_f, gxf, S_LEN * BB, G3, EMBD, 1), 1);
    gemm1(mk(emb, EMBD, enc_wx_b, EMBD, 0, enc_bx_b, gxb, S_LEN * BB, G3, EMBD, 1), 1);

    cudaMemsetAsync(hf, 0, (size_t)BB * HIDN * sizeof(float));
    cudaMemsetAsync(hb, 0, (size_t)BB * HIDN * sizeof(float));

    for (int s = 0; s < S_LEN; s++) {
        int sb = S_LEN - 1 - s;   // backward timestep
        GArgs gf = mk(hf, HIDN, enc_wh_f, HIDN, 0, nullptr, pa, BB, G3, HIDN, 4);
        GArgs gb = mk(hb, HIDN, enc_wh_b, HIDN, 0, nullptr, pb, BB, G3, HIDN, 4);
        gemm2(gf, gb, 4);
        gru_gate2_k<<<up(2 * BB * HIDN, 256), 256>>>(
            gxf + (size_t)s * BB * G3, gxb + (size_t)sb * BB * G3,
            pa, pb, 4, enc_bh_f, enc_bh_b, hf, hb,
            enc + (size_t)s * BB * E2, enc + (size_t)sb * BB * E2 + HIDN);
    }

    // hidden = tanh(hb @ enc_fc_w^T + b)
    gemm1(mk(hb, HIDN, enc_fc_w, HIDN, 0, nullptr, pa, BB, HIDN, HIDN, 8), 8);
    finalize_k<<<up(BB * HIDN, 256), 256>>>(pa, 8, enc_fc_b, hd, BB * HIDN, HIDN, 1);
    // e_part = enc_out @ aw_e^T (attn_w cols [HID:3HID])
    gemm1(mk(enc, E2, attn_w, G3, HIDN, nullptr, ep, S_LEN * BB, ATTD, E2, 1), 1);

    // ---------------- Decoder ----------------
    copy_inp_k<<<1, BB>>>(trg, inp);
    for (int t = 0; t < T_LEN - 1; t++) {
        // hq partials = hd @ aw_h^T
        gemm1(mk(hd, HIDN, attn_w, G3, 0, nullptr, pa, BB, ATTD, HIDN, 8), 8);
        attention_k<<<BB, 256>>>(pa, ep, attn_b, attn_v, enc, dec_emb, inp, x, mi);
        // gx = x @ dec_wx^T ; gh = hd @ dec_wh^T  (one dual launch)
        GArgs ga = mk(x,  DXK,  dec_wx, DXK,  0, nullptr, pa, BB, G3, DXK,  8);
        GArgs gh = mk(hd, HIDN, dec_wh, HIDN, 0, nullptr, pb, BB, G3, HIDN, 8);
        gemm2(ga, gh, 8);
        gru_gate_k<<<up(BB * HIDN, 256), 256>>>(pa, 8, dec_bx, pb, 8, dec_bh, hd, mi, MXK);
        gemm1(mk(mi, MXK, max_w, MXK, 0, nullptr, pm, BB, MX2, MXK, 16), 16);
        finalize_max_k<<<up(BB * MXO, 256), 256>>>(pm, 16, max_b, tm);
        float* pred = out + (size_t)(t + 1) * BB * OUTV;
        gemm1(mk(tm, MXO, out_w, MXO, 0, out_b, pred, BB, OUTV, MXO, 1), 1);
        argmax_k<<<BB, 256>>>(pred, inp);
    }
}